// round 1
// baseline (speedup 1.0000x reference)
#include <cuda_runtime.h>
#include <cstdint>

#define BM 128
#define BN 64
#define BK 32
#define NTH 256

__device__ __forceinline__ unsigned long long pack2(float lo, float hi) {
    unsigned long long r;
    asm("mov.b64 %0, {%1, %2};" : "=l"(r) : "r"(__float_as_uint(lo)), "r"(__float_as_uint(hi)));
    return r;
}
__device__ __forceinline__ void unpack2(unsigned long long v, float& lo, float& hi) {
    unsigned int a, b;
    asm("mov.b64 {%0, %1}, %2;" : "=r"(a), "=r"(b) : "l"(v));
    lo = __uint_as_float(a);
    hi = __uint_as_float(b);
}
__device__ __forceinline__ void fma2(unsigned long long& d, unsigned long long a, unsigned long long b) {
    asm("fma.rn.f32x2 %0, %1, %2, %0;" : "+l"(d) : "l"(a), "l"(b));
}

extern "C" __global__ void __launch_bounds__(NTH, 1)
router_kernel(const float* __restrict__ x, const float* __restrict__ W,
              float* __restrict__ out, int T, int H, int writeAux)
{
    // smem: GEMM phase uses [2][BK][BM] x-tiles + [2][BK][BN] w-tiles = 12288 floats (48KB)
    // epilogue phase overlays logits [64][129] + M[128] + Rinv[128] on the same storage.
    __shared__ float sm[2 * BK * BM + 2 * BK * BN];
    float* xs = sm;                    // [2][BK][BM]  (k-major, token contiguous)
    float* ws = sm + 2 * BK * BM;      // [2][BK][BN]

    const int tid = threadIdx.x;
    const int m0  = blockIdx.x * BM;

    // --- global-load mapping ---
    const int xt = tid & 127;          // token row for x loads
    const int xq = tid >> 7;           // quad phase 0..1 (quads q = xq + 2r, r=0..3)
    const int we = tid & 63;           // expert row for W loads
    const int wq = tid >> 6;           // quad phase 0..3 (quads q = wq + 4r, r=0..1)

    // --- compute mapping: 16 token-groups x 16 expert-groups ---
    const int mt = tid & 15;           // owns tokens mt*8 .. mt*8+7
    const int et = tid >> 4;           // owns experts et*4 .. et*4+3

    unsigned long long acc[4][4];      // acc[expert i][token-pair j]
#pragma unroll
    for (int i = 0; i < 4; i++)
#pragma unroll
        for (int j = 0; j < 4; j++) acc[i][j] = 0ULL;

    const float* xrow = x + (size_t)(m0 + xt) * H;
    const float* wrow = W + (size_t)we * H;
    const int nch = H / BK;

    float4 xr[4];
    float4 wr[2];

    auto ldg = [&](int c) {
        const float* xp = xrow + c * BK;
#pragma unroll
        for (int r = 0; r < 4; r++)
            xr[r] = *(const float4*)(xp + 4 * (xq + 2 * r));
        const float* wp = wrow + c * BK;
#pragma unroll
        for (int r = 0; r < 2; r++)
            wr[r] = *(const float4*)(wp + 4 * (wq + 4 * r));
    };

    auto sts = [&](int b) {
        float* xb = xs + b * BK * BM;
#pragma unroll
        for (int r = 0; r < 4; r++) {
            int q = xq + 2 * r;
            xb[(4 * q + 0) * BM + xt] = xr[r].x;
            xb[(4 * q + 1) * BM + xt] = xr[r].y;
            xb[(4 * q + 2) * BM + xt] = xr[r].z;
            xb[(4 * q + 3) * BM + xt] = xr[r].w;
        }
        float* wb = ws + b * BK * BN;
#pragma unroll
        for (int r = 0; r < 2; r++) {
            int q = wq + 4 * r;
            wb[(4 * q + 0) * BN + we] = wr[r].x;
            wb[(4 * q + 1) * BN + we] = wr[r].y;
            wb[(4 * q + 2) * BN + we] = wr[r].z;
            wb[(4 * q + 3) * BN + we] = wr[r].w;
        }
    };

    auto comp = [&](int b) {
        const float* xb = xs + b * BK * BM;
        const float* wb = ws + b * BK * BN;
#pragma unroll 8
        for (int kk = 0; kk < BK; kk++) {
            float4 wf = *(const float4*)(wb + kk * BN + et * 4);
            unsigned long long w2[4];
            w2[0] = pack2(wf.x, wf.x);
            w2[1] = pack2(wf.y, wf.y);
            w2[2] = pack2(wf.z, wf.z);
            w2[3] = pack2(wf.w, wf.w);
            const unsigned long long* xp =
                (const unsigned long long*)(xb + kk * BM + mt * 8);
#pragma unroll
            for (int j = 0; j < 4; j++) {
                unsigned long long xv = xp[j];   // tokens (mt*8+2j, mt*8+2j+1)
#pragma unroll
                for (int i = 0; i < 4; i++) fma2(acc[i][j], w2[i], xv);
            }
        }
    };

    // --- pipelined mainloop ---
    ldg(0);
    sts(0);
    __syncthreads();
    int buf = 0;
    for (int c = 1; c < nch; ++c) {
        ldg(c);            // fetch chunk c into registers (latency hidden by comp)
        comp(buf);         // compute chunk c-1
        __syncthreads();
        sts(buf ^ 1);      // commit chunk c
        __syncthreads();
        buf ^= 1;
    }
    comp(buf);             // last chunk
    __syncthreads();

    // --- epilogue: logits -> smem transposed [64][129] (pad kills conflicts) ---
    float* sl = sm;
#pragma unroll
    for (int i = 0; i < 4; i++) {
        int e = et * 4 + i;
#pragma unroll
        for (int j = 0; j < 4; j++) {
            float lo, hi;
            unpack2(acc[i][j], lo, hi);
            sl[e * 129 + mt * 8 + 2 * j]     = lo;
            sl[e * 129 + mt * 8 + 2 * j + 1] = hi;
        }
    }
    float* Ms = sm + 64 * 129;   // [128] row max
    float* Rs = Ms + 128;        // [128] 1/sum(exp)
    __syncthreads();

    if (tid < BM) {
        float v1 = -1e30f, v2 = -1e30f;
        int i1 = 0, i2 = 0;
#pragma unroll
        for (int e = 0; e < 64; e++) {
            float v = sl[e * 129 + tid];
            if (v > v1) { v2 = v1; i2 = i1; v1 = v; i1 = e; }
            else if (v > v2) { v2 = v; i2 = e; }
        }
        float s = 0.f;
#pragma unroll
        for (int e = 0; e < 64; e++) s += expf(sl[e * 129 + tid] - v1);
        float rinv = 1.f / s;
        Ms[tid] = v1;
        Rs[tid] = rinv;

        if (writeAux) {
            // expert weights: softmax top-2, L1-normalized -> e1/(e1+e2), e2/(e1+e2)
            float e1 = 1.f;                 // exp(v1 - v1)
            float e2 = expf(v2 - v1);
            float wsum = e1 + e2;
            int t = m0 + tid;
            float* wout = out + (size_t)T * 64;
            wout[2 * t]     = e1 / wsum;
            wout[2 * t + 1] = e2 / wsum;
            float* iout = out + (size_t)T * 64 + (size_t)T * 2;
            iout[2 * t]     = (float)i1;
            iout[2 * t + 1] = (float)i2;
        }
    }
    __syncthreads();

    // --- coalesced softmax score writes: [T, 64] ---
    for (int idx = tid; idx < BM * 64; idx += NTH) {
        int tt = idx >> 6;
        int e  = idx & 63;
        out[(size_t)(m0 + tt) * 64 + e] = expf(sl[e * 129 + tt] - Ms[tt]) * Rs[tt];
    }
}

extern "C" void kernel_launch(void* const* d_in, const int* in_sizes, int n_in,
                              void* d_out, int out_size)
{
    const float* x = (const float*)d_in[0];
    const float* W = (const float*)d_in[1];
    const int E = 64;
    const int H = in_sizes[1] / E;            // 4096
    const int T = in_sizes[0] / H;            // 16384
    const int writeAux = (out_size >= T * E + 4 * T) ? 1 : 0;

    router_kernel<<<T / BM, NTH>>>(x, W, (float*)d_out, T, H, writeAux);
}

// round 3
// speedup vs baseline: 3.9958x; 3.9958x over previous
#include <cuda_runtime.h>
#include <cuda_fp16.h>
#include <cstdint>

#define NTH 256
#define BM  128
#define BK  64    // k-floats per chunk (=64 halfs, 128B rows)

// dynamic smem: per buffer 48KB
#define OFF_AHI(b) ((b)*49152 + 0)       // [128][64] half
#define OFF_ALO(b) ((b)*49152 + 16384)
#define OFF_BHI(b) ((b)*49152 + 32768)   // [64][64] half
#define OFF_BLO(b) ((b)*49152 + 40960)
#define SMEM_BYTES 98304

__device__ __forceinline__ uint32_t swz(uint32_t off) {
    return off ^ ((off >> 3) & 0x70);    // SW128: XOR row&7 into 16B-chunk bits
}

__device__ __forceinline__ uint32_t s2u(const void* p) {
    uint32_t a;
    asm("{ .reg .u64 t; cvta.to.shared.u64 t, %1; cvt.u32.u64 %0, t; }"
        : "=r"(a) : "l"(p));
    return a;
}

__device__ __forceinline__ void ldmx4(uint32_t* r, uint32_t addr) {
    asm volatile("ldmatrix.sync.aligned.m8n8.x4.shared.b16 {%0,%1,%2,%3}, [%4];"
                 : "=r"(r[0]), "=r"(r[1]), "=r"(r[2]), "=r"(r[3]) : "r"(addr));
}

__device__ __forceinline__ void mma16816(float* d, const uint32_t* a, const uint32_t* b) {
    asm volatile(
        "mma.sync.aligned.m16n8k16.row.col.f32.f16.f16.f32 "
        "{%0,%1,%2,%3}, {%4,%5,%6,%7}, {%8,%9}, {%0,%1,%2,%3};"
        : "+f"(d[0]), "+f"(d[1]), "+f"(d[2]), "+f"(d[3])
        : "r"(a[0]), "r"(a[1]), "r"(a[2]), "r"(a[3]), "r"(b[0]), "r"(b[1]));
}

// split float2 -> (hi half2, lo half2)
__device__ __forceinline__ void split2(float fx, float fy, uint32_t& hi, uint32_t& lo) {
    __half2 h = __floats2half2_rn(fx, fy);
    float2 hf = __half22float2(h);
    __half2 l = __floats2half2_rn(fx - hf.x, fy - hf.y);
    hi = *reinterpret_cast<uint32_t*>(&h);
    lo = *reinterpret_cast<uint32_t*>(&l);
}

extern "C" __global__ void __launch_bounds__(NTH, 1)
router_mma(const float* __restrict__ x, const float* __restrict__ W,
           float* __restrict__ out, int T, int H, int writeAux)
{
    extern __shared__ __align__(1024) char sm[];
    const uint32_t sb = s2u(sm);
    const int tid = threadIdx.x;
    const int wid = tid >> 5;
    const int lid = tid & 31;
    const int m0  = blockIdx.x * BM;
    const int nch = H / BK;            // 64

    const int wr = wid & 3;            // m-row of warp grid (4)
    const int wc = wid >> 2;           // n-col of warp grid (2)

    float acc[2][4][4];
#pragma unroll
    for (int mi = 0; mi < 2; mi++)
#pragma unroll
        for (int ni = 0; ni < 4; ni++)
#pragma unroll
            for (int k = 0; k < 4; k++) acc[mi][ni][k] = 0.f;

    // ---- staging regs ----
    float4 xr[8];
    float4 wreg[4];

    const int xm = tid >> 4;           // token row handled for x loads (2/thread-warp…)
    const int xq = tid & 15;           // float4 index within the 64-float row
    const float* xrow0 = x + (size_t)(m0 + (tid >> 4)) * H + (tid & 15) * 4;
    const float* xrow1 = x + (size_t)(m0 + (tid >> 4) + 16) * H + (tid & 15) * 4; (void)xrow1;

    auto ldg = [&](int c) {
        const int kb = c * BK;
#pragma unroll
        for (int i = 0; i < 8; i++) {
            int idx = tid + i * NTH;
            int m = idx >> 4, kq = idx & 15;
            xr[i] = *(const float4*)(x + (size_t)(m0 + m) * H + kb + kq * 4);
        }
#pragma unroll
        for (int i = 0; i < 4; i++) {
            int idx = tid + i * NTH;
            int e = idx >> 4, kq = idx & 15;
            wreg[i] = *(const float4*)(W + (size_t)e * H + kb + kq * 4);
        }
    };

    auto sts = [&](int b) {
#pragma unroll
        for (int i = 0; i < 8; i++) {
            int idx = tid + i * NTH;
            int m = idx >> 4, kq = idx & 15;
            uint32_t ph = swz((uint32_t)(m * 128 + kq * 8));
            uint2 hi, lo;
            split2(xr[i].x, xr[i].y, hi.x, lo.x);
            split2(xr[i].z, xr[i].w, hi.y, lo.y);
            *(uint2*)(sm + OFF_AHI(b) + ph) = hi;
            *(uint2*)(sm + OFF_ALO(b) + ph) = lo;
        }
#pragma unroll
        for (int i = 0; i < 4; i++) {
            int idx = tid + i * NTH;
            int e = idx >> 4, kq = idx & 15;
            uint32_t ph = swz((uint32_t)(e * 128 + kq * 8));
            uint2 hi, lo;
            split2(wreg[i].x, wreg[i].y, hi.x, lo.x);
            split2(wreg[i].z, wreg[i].w, hi.y, lo.y);
            *(uint2*)(sm + OFF_BHI(b) + ph) = hi;
            *(uint2*)(sm + OFF_BLO(b) + ph) = lo;
        }
    };

    // per-thread base offsets for ldmatrix (row part; col added per ks)
    // A frag (mt, split): rows mt*16 + (l&7) + ((l>>3)&1)*8 ; col (l>>4)*16 + ks*32
    uint32_t a_row[2];
#pragma unroll
    for (int mi = 0; mi < 2; mi++)
        a_row[mi] = (uint32_t)(((wr * 2 + mi) * 16 + (lid & 7) + ((lid >> 3) & 1) * 8) * 128
                               + (lid >> 4) * 16);
    // B frag pair h (n-tiles 2h,2h+1): rows wc*32 + h*16 + ((l>>4)&1)*8 + (l&7); col ((l>>3)&1)*16 + ks*32
    uint32_t b_row[2];
#pragma unroll
    for (int h = 0; h < 2; h++)
        b_row[h] = (uint32_t)((wc * 32 + h * 16 + ((lid >> 4) & 1) * 8 + (lid & 7)) * 128
                              + ((lid >> 3) & 1) * 16);

    auto comp = [&](int b) {
        const uint32_t ah_base = sb + OFF_AHI(b), al_base = sb + OFF_ALO(b);
        const uint32_t bh_base = sb + OFF_BHI(b), bl_base = sb + OFF_BLO(b);
#pragma unroll
        for (int ks = 0; ks < 4; ks++) {
            uint32_t ah[2][4], al[2][4];
#pragma unroll
            for (int mi = 0; mi < 2; mi++) {
                uint32_t off = a_row[mi] + ks * 32;
                uint32_t ph = swz(off);
                ldmx4(ah[mi], ah_base + ph);
                ldmx4(al[mi], al_base + ph);
            }
            uint32_t bh[2][4], bl[2][4];
#pragma unroll
            for (int h = 0; h < 2; h++) {
                uint32_t off = b_row[h] + ks * 32;
                uint32_t ph = swz(off);
                ldmx4(bh[h], bh_base + ph);
                ldmx4(bl[h], bl_base + ph);
            }
#pragma unroll
            for (int mi = 0; mi < 2; mi++)
#pragma unroll
                for (int ni = 0; ni < 4; ni++) {
                    const uint32_t* bhp = &bh[ni >> 1][(ni & 1) * 2];
                    const uint32_t* blp = &bl[ni >> 1][(ni & 1) * 2];
                    mma16816(acc[mi][ni], ah[mi], bhp);   // xh*wh
                    mma16816(acc[mi][ni], ah[mi], blp);   // xh*wl
                    mma16816(acc[mi][ni], al[mi], bhp);   // xl*wh
                }
        }
    };

    // ---- pipelined mainloop ----
    ldg(0);
    sts(0);
    __syncthreads();
    int buf = 0;
    for (int c = 1; c < nch; ++c) {
        ldg(c);
        comp(buf);
        __syncthreads();
        sts(buf ^ 1);
        __syncthreads();
        buf ^= 1;
    }
    comp(buf);
    __syncthreads();

    // ---- epilogue: scatter accs into sl[e][t] (pad 129 kills conflicts) ----
    float* sl = (float*)sm;            // [64][129] + Ms[128] + Rs[128]
    {
        const int r = lid >> 2;
        const int c0 = (lid & 3) * 2;
#pragma unroll
        for (int mi = 0; mi < 2; mi++) {
            const int tb = wr * 32 + mi * 16;
#pragma unroll
            for (int ni = 0; ni < 4; ni++) {
                const int eb = wc * 32 + ni * 8 + c0;
                sl[(eb + 0) * 129 + tb + r]     = acc[mi][ni][0];
                sl[(eb + 1) * 129 + tb + r]     = acc[mi][ni][1];
                sl[(eb + 0) * 129 + tb + r + 8] = acc[mi][ni][2];
                sl[(eb + 1) * 129 + tb + r + 8] = acc[mi][ni][3];
            }
        }
    }
    float* Ms = sl + 64 * 129;
    float* Rs = Ms + 128;
    __syncthreads();

    if (tid < BM) {
        float v1 = -1e30f, v2 = -1e30f;
        int i1 = 0, i2 = 0;
#pragma unroll
        for (int e = 0; e < 64; e++) {
            float v = sl[e * 129 + tid];
            if (v > v1)      { v2 = v1; i2 = i1; v1 = v; i1 = e; }
            else if (v > v2) { v2 = v;  i2 = e; }
        }
        float s = 0.f;
#pragma unroll
        for (int e = 0; e < 64; e++) s += expf(sl[e * 129 + tid] - v1);
        float rinv = 1.f / s;
        Ms[tid] = v1;
        Rs[tid] = rinv;

        if (writeAux) {
            float e2 = expf(v2 - v1);
            float wsum = 1.f + e2;
            int t = m0 + tid;
            float* wout = out + (size_t)T * 64;
            wout[2 * t]     = 1.f / wsum;
            wout[2 * t + 1] = e2 / wsum;
            float* iout = out + (size_t)T * 64 + (size_t)T * 2;
            iout[2 * t]     = (float)i1;
            iout[2 * t + 1] = (float)i2;
        }
    }
    __syncthreads();

    for (int idx = tid; idx < BM * 64; idx += NTH) {
        int tt = idx >> 6;
        int e  = idx & 63;
        out[(size_t)(m0 + tt) * 64 + e] = expf(sl[e * 129 + tt] - Ms[tt]) * Rs[tt];
    }
}

extern "C" void kernel_launch(void* const* d_in, const int* in_sizes, int n_in,
                              void* d_out, int out_size)
{
    const float* x = (const float*)d_in[0];
    const float* W = (const float*)d_in[1];
    const int E = 64;
    const int H = in_sizes[1] / E;     // 4096
    const int T = in_sizes[0] / H;     // 16384
    const int writeAux = (out_size >= T * E + 4 * T) ? 1 : 0;

    cudaFuncSetAttribute(router_mma, cudaFuncAttributeMaxDynamicSharedMemorySize, SMEM_BYTES);
    router_mma<<<T / BM, NTH, SMEM_BYTES>>>(x, W, (float*)d_out, T, H, writeAux);
}

// round 5
// speedup vs baseline: 4.7489x; 1.1885x over previous
#include <cuda_runtime.h>
#include <cuda_fp16.h>
#include <cstdint>

#define NTH 512
#define BM  128
#define BKF 32                     // k-floats per chunk

// pre-split W: [128 chunks][64 experts][128B: 32 hi halfs | 32 lo halfs]
__device__ __align__(128) uint8_t g_wsp[1 << 20];

#define OFF_A(g,s) ((g)*73728 + (s)*16384)            // [128 rows][128B: hi|lo]
#define OFF_B(g,s) ((g)*73728 + 49152 + (s)*8192)     // [64 rows][128B: hi|lo]
#define SMEM_BYTES 147456

__device__ __forceinline__ uint32_t swz(uint32_t off) {
    return off ^ ((off >> 3) & 0x70);
}
__device__ __forceinline__ uint32_t s2u(const void* p) {
    uint32_t a;
    asm("{ .reg .u64 t; cvta.to.shared.u64 t, %1; cvt.u32.u64 %0, t; }"
        : "=r"(a) : "l"(p));
    return a;
}
__device__ __forceinline__ void ldmx4(uint32_t* r, uint32_t addr) {
    asm volatile("ldmatrix.sync.aligned.m8n8.x4.shared.b16 {%0,%1,%2,%3}, [%4];"
                 : "=r"(r[0]), "=r"(r[1]), "=r"(r[2]), "=r"(r[3]) : "r"(addr));
}
__device__ __forceinline__ void mma16816(float* d, const uint32_t* a, const uint32_t* b) {
    asm volatile(
        "mma.sync.aligned.m16n8k16.row.col.f32.f16.f16.f32 "
        "{%0,%1,%2,%3}, {%4,%5,%6,%7}, {%8,%9}, {%0,%1,%2,%3};"
        : "+f"(d[0]), "+f"(d[1]), "+f"(d[2]), "+f"(d[3])
        : "r"(a[0]), "r"(a[1]), "r"(a[2]), "r"(a[3]), "r"(b[0]), "r"(b[1]));
}
__device__ __forceinline__ void split2(float fx, float fy, uint32_t& hi, uint32_t& lo) {
    __half2 h = __floats2half2_rn(fx, fy);
    float2 hf = __half22float2(h);
    __half2 l = __floats2half2_rn(fx - hf.x, fy - hf.y);
    hi = *reinterpret_cast<uint32_t*>(&h);
    lo = *reinterpret_cast<uint32_t*>(&l);
}
__device__ __forceinline__ void cpasync16(uint32_t dst, const void* src) {
    asm volatile("cp.async.cg.shared.global [%0], [%1], 16;" :: "r"(dst), "l"(src));
}
#define CP_COMMIT() asm volatile("cp.async.commit_group;" ::: "memory")
#define CP_WAIT(n)  asm volatile("cp.async.wait_group %0;" :: "n"(n) : "memory")
#define GBAR(id)    asm volatile("bar.sync %0, 256;" :: "r"(id) : "memory")

// ---------- pre-kernel: split W into fp16 hi/lo, cp.async-ready layout ----------
extern "C" __global__ void wsplit_kernel(const float* __restrict__ W) {
    int idx = blockIdx.x * blockDim.x + threadIdx.x;   // 65536
    int e    = idx >> 10;
    int rem  = idx & 1023;
    int c    = rem >> 3;
    int sub  = rem & 7;
    int q    = sub & 3;
    int isLo = sub >> 2;
    const float* src = W + (size_t)e * 4096 + c * 32 + q * 8;
    __half h[8];
#pragma unroll
    for (int i = 0; i < 8; i++) {
        float v = src[i];
        __half hi = __float2half_rn(v);
        h[i] = isLo ? __float2half_rn(v - __half2float(hi)) : hi;
    }
    *(uint4*)(g_wsp + (size_t)c * 8192 + e * 128 + isLo * 64 + q * 16) = *(uint4*)h;
}

// ---------- main kernel ----------
extern "C" __global__ void __launch_bounds__(NTH, 1)
router_mma2(const float* __restrict__ x, float* __restrict__ out,
            int T, int H, int writeAux)
{
    extern __shared__ __align__(1024) char sm[];
    const uint32_t sb = s2u(sm);
    const int tid  = threadIdx.x;
    const int gid  = tid >> 8;          // k-group 0/1
    const int gtid = tid & 255;
    const int gw   = gtid >> 5;         // warp in group
    const int lid  = tid & 31;
    const int wr   = gw & 3, wc = gw >> 2;
    const int m0   = blockIdx.x * BM;
    const int barid = 1 + gid;

    float acc[2][4][4];
#pragma unroll
    for (int mi = 0; mi < 2; mi++)
#pragma unroll
        for (int ni = 0; ni < 4; ni++)
#pragma unroll
            for (int k = 0; k < 4; k++) acc[mi][ni][k] = 0.f;

    // per-thread A staging mapping: fixed q, rows mb+32n
    const int q  = gtid & 7;
    const int mb = gtid >> 3;
    const float* xbase = x + (size_t)(m0 + mb) * H + q * 4;
    const uint32_t sA_hi = swz((uint32_t)(mb * 128 + q * 8));        // +n*32*128 later (row-stride add: safe, no XOR-bit carry)
    const uint32_t sA_lo = swz((uint32_t)(mb * 128 + 64 + q * 8));

    float4 R[4];
    auto ldgA = [&](int ch) {
        const float* p = xbase + ch * BKF;
#pragma unroll
        for (int n = 0; n < 4; n++)
            R[n] = *(const float4*)(p + (size_t)(32 * n) * H);
    };
    auto stsA = [&](int s) {
        char* base = sm + OFF_A(gid, s);
#pragma unroll
        for (int n = 0; n < 4; n++) {
            uint2 hi, lo;
            split2(R[n].x, R[n].y, hi.x, lo.x);
            split2(R[n].z, R[n].w, hi.y, lo.y);
            *(uint2*)(base + sA_hi + n * 32 * 128) = hi;   // row-offset add only touches bits >=12: swizzle-safe
            *(uint2*)(base + sA_lo + n * 32 * 128) = lo;
        }
    };
    auto cpB = [&](int ch, int s) {
        uint32_t dstb = sb + OFF_B(gid, s);
        const uint8_t* srcb = g_wsp + (size_t)ch * 8192;
#pragma unroll
        for (int n = 0; n < 2; n++) {
            int e = mb + 32 * n;
            cpasync16(dstb + swz((uint32_t)(e * 128 + q * 16)),
                      srcb + e * 128 + q * 16);
        }
        CP_COMMIT();
    };

    // UN-swizzled per-thread ldmatrix base offsets; swizzle applied per access
    // (swz(base+delta) != swz(base)+delta when delta hits the XORed chunk bits).
    uint32_t oA[2], oB[2];
#pragma unroll
    for (int mi = 0; mi < 2; mi++)
        oA[mi] = (uint32_t)(((wr * 2 + mi) * 16 + (lid & 7) + ((lid >> 3) & 1) * 8) * 128
                            + (lid >> 4) * 16);
#pragma unroll
    for (int h = 0; h < 2; h++)
        oB[h] = (uint32_t)((wc * 32 + h * 16 + ((lid >> 4) & 1) * 8 + (lid & 7)) * 128
                           + ((lid >> 3) & 1) * 16);

    auto comp = [&](int s) {
        const uint32_t Ab = sb + OFF_A(gid, s);
        const uint32_t Bb = sb + OFF_B(gid, s);
#pragma unroll
        for (int ks = 0; ks < 2; ks++) {
            uint32_t ah[2][4], al[2][4], bh[2][4], bl[2][4];
#pragma unroll
            for (int mi = 0; mi < 2; mi++) {
                ldmx4(ah[mi], Ab + swz(oA[mi] + ks * 32));
                ldmx4(al[mi], Ab + swz(oA[mi] + ks * 32 + 64));
            }
#pragma unroll
            for (int h = 0; h < 2; h++) {
                ldmx4(bh[h], Bb + swz(oB[h] + ks * 32));
                ldmx4(bl[h], Bb + swz(oB[h] + ks * 32 + 64));
            }
#pragma unroll
            for (int mi = 0; mi < 2; mi++)
#pragma unroll
                for (int ni = 0; ni < 4; ni++) {
                    const uint32_t* bhp = &bh[ni >> 1][(ni & 1) * 2];
                    const uint32_t* blp = &bl[ni >> 1][(ni & 1) * 2];
                    mma16816(acc[mi][ni], ah[mi], bhp);
                    mma16816(acc[mi][ni], ah[mi], blp);
                    mma16816(acc[mi][ni], al[mi], bhp);
                }
        }
    };

    // ---- prologue: chunks ch(j)=2j+gid; stage s=j%3 ----
    cpB(gid, 0);
    cpB(2 + gid, 1);
    ldgA(gid);      stsA(0);
    ldgA(2 + gid);  stsA(1);
    ldgA(4 + gid);               // chunk j=2 stays in R
    CP_WAIT(1);                  // B(j=0) complete
    GBAR(barid);

    // ---- mainloop: 64 iterations per group ----
    for (int j = 0; j < 64; j++) {
        const int s = j % 3;
        if (j < 62) {
            const int s2 = (j + 2) % 3;
            cpB(2 * (j + 2) + gid, s2);
            stsA(s2);                              // chunk j+2, regs from last iter
            if (j < 61) ldgA(2 * (j + 3) + gid);   // chunk j+3 into R
            CP_WAIT(1);                            // B(j+1) complete
        } else {
            CP_WAIT(0);
        }
        comp(s);
        GBAR(barid);
    }

    __syncthreads();

    // ---- epilogue: cross-group reduction into sl[e][t] ----
    float* sl = (float*)sm;          // [64][129] + Ms[128] + Rs[128]
    const int rr = lid >> 2;
    const int c0 = (lid & 3) * 2;
    if (gid == 0) {
#pragma unroll
        for (int mi = 0; mi < 2; mi++) {
            const int tb = wr * 32 + mi * 16;
#pragma unroll
            for (int ni = 0; ni < 4; ni++) {
                const int eb = wc * 32 + ni * 8 + c0;
                sl[(eb + 0) * 129 + tb + rr]     = acc[mi][ni][0];
                sl[(eb + 1) * 129 + tb + rr]     = acc[mi][ni][1];
                sl[(eb + 0) * 129 + tb + rr + 8] = acc[mi][ni][2];
                sl[(eb + 1) * 129 + tb + rr + 8] = acc[mi][ni][3];
            }
        }
    }
    __syncthreads();
    if (gid == 1) {
#pragma unroll
        for (int mi = 0; mi < 2; mi++) {
            const int tb = wr * 32 + mi * 16;
#pragma unroll
            for (int ni = 0; ni < 4; ni++) {
                const int eb = wc * 32 + ni * 8 + c0;
                sl[(eb + 0) * 129 + tb + rr]     += acc[mi][ni][0];
                sl[(eb + 1) * 129 + tb + rr]     += acc[mi][ni][1];
                sl[(eb + 0) * 129 + tb + rr + 8] += acc[mi][ni][2];
                sl[(eb + 1) * 129 + tb + rr + 8] += acc[mi][ni][3];
            }
        }
    }
    float* Ms = sl + 64 * 129;
    float* Rs = Ms + 128;
    __syncthreads();

    if (tid < BM) {
        float v1 = -1e30f, v2 = -1e30f;
        int i1 = 0, i2 = 0;
#pragma unroll
        for (int e = 0; e < 64; e++) {
            float v = sl[e * 129 + tid];
            if (v > v1)      { v2 = v1; i2 = i1; v1 = v; i1 = e; }
            else if (v > v2) { v2 = v;  i2 = e; }
        }
        float ssum = 0.f;
#pragma unroll
        for (int e = 0; e < 64; e++) ssum += expf(sl[e * 129 + tid] - v1);
        float rinv = 1.f / ssum;
        Ms[tid] = v1;
        Rs[tid] = rinv;

        if (writeAux) {
            float e2 = expf(v2 - v1);
            float wsum = 1.f + e2;
            int t = m0 + tid;
            float* wout = out + (size_t)T * 64;
            wout[2 * t]     = 1.f / wsum;
            wout[2 * t + 1] = e2 / wsum;
            float* iout = out + (size_t)T * 64 + (size_t)T * 2;
            iout[2 * t]     = (float)i1;
            iout[2 * t + 1] = (float)i2;
        }
    }
    __syncthreads();

    for (int idx = tid; idx < BM * 64; idx += NTH) {
        int tt = idx >> 6;
        int e  = idx & 63;
        out[(size_t)(m0 + tt) * 64 + e] = expf(sl[e * 129 + tt] - Ms[tt]) * Rs[tt];
    }
}

extern "C" void kernel_launch(void* const* d_in, const int* in_sizes, int n_in,
                              void* d_out, int out_size)
{
    const float* x = (const float*)d_in[0];
    const float* W = (const float*)d_in[1];
    const int E = 64;
    const int H = in_sizes[1] / E;     // 4096
    const int T = in_sizes[0] / H;     // 16384
    const int writeAux = (out_size >= T * E + 4 * T) ? 1 : 0;

    wsplit_kernel<<<256, 256>>>(W);
    cudaFuncSetAttribute(router_mma2, cudaFuncAttributeMaxDynamicSharedMemorySize, SMEM_BYTES);
    router_mma2<<<T / BM, NTH, SMEM_BYTES>>>(x, (float*)d_out, T, H, writeAux);
}